// round 8
// baseline (speedup 1.0000x reference)
#include <cuda_runtime.h>
#include <cstdint>

// ---------------- problem constants ----------------
static constexpr int MDIM = 4096;   // batch
static constexpr int NDIM = 4096;   // out features
static constexpr int KDIM = 4096;   // in features

static constexpr int BM = 128;
static constexpr int BN = 128;
static constexpr int BK = 32;
static constexpr int STAGES  = 3;
static constexpr int THREADS = 256;          // 8 warps: 4 (m) x 2 (n), warp tile 32x64
static constexpr int KITERS  = KDIM / BK;    // 128

static constexpr uint32_t ASTAGE = BM * BK * 4;            // 16 KB
static constexpr uint32_t BSTAGE = BN * BK * 4;            // 16 KB
static constexpr uint32_t SLOT   = ASTAGE + BSTAGE;        // 32 KB
static constexpr uint32_t SMEM_TOTAL = STAGES * SLOT;      // 96 KB -> 2 CTAs/SM

// ---------------- scratch (device globals: allocations are banned) ----------------
__device__ __align__(1024) float g_wm[(size_t)NDIM * KDIM];  // tf32-rounded masked weight

// ---------------- sm_80-safe PTX helpers ----------------
__device__ __forceinline__ uint32_t smem_u32(const void* p) {
    uint32_t a;
    asm("{ .reg .u64 t; cvta.to.shared.u64 t, %1; cvt.u32.u64 %0, t; }" : "=r"(a) : "l"(p));
    return a;
}
__device__ __forceinline__ void cp_async16(uint32_t dst, const void* src) {
    asm volatile("cp.async.cg.shared.global [%0], [%1], 16;" :: "r"(dst), "l"(src) : "memory");
}
__device__ __forceinline__ void cp_commit() {
    asm volatile("cp.async.commit_group;" ::: "memory");
}
template <int N>
__device__ __forceinline__ void cp_wait() {
    asm volatile("cp.async.wait_group %0;" :: "n"(N) : "memory");
}
__device__ __forceinline__ void ldsm_x4(uint32_t* r, uint32_t addr) {
    asm volatile("ldmatrix.sync.aligned.m8n8.x4.shared.b16 {%0,%1,%2,%3}, [%4];"
                 : "=r"(r[0]), "=r"(r[1]), "=r"(r[2]), "=r"(r[3]) : "r"(addr));
}
__device__ __forceinline__ void mma_tf32(float* c, const uint32_t* a, const uint32_t* b) {
    asm volatile(
        "mma.sync.aligned.m16n8k8.row.col.f32.tf32.tf32.f32 "
        "{%0,%1,%2,%3}, {%4,%5,%6,%7}, {%8,%9}, {%0,%1,%2,%3};"
        : "+f"(c[0]), "+f"(c[1]), "+f"(c[2]), "+f"(c[3])
        : "r"(a[0]), "r"(a[1]), "r"(a[2]), "r"(a[3]), "r"(b[0]), "r"(b[1]));
}
__device__ __forceinline__ float tf32_rna(float f) {
    uint32_t o, i = __float_as_uint(f);
    asm("cvt.rna.tf32.f32 %0, %1;" : "=r"(o) : "r"(i));
    return __uint_as_float(o);
}

// ---------------- prep: masked weight with tf32 RNA rounding ----------------
__global__ void prep_kernel(const float4* __restrict__ w, const float4* __restrict__ msk,
                            float4* __restrict__ wm, int n4) {
    int stride = gridDim.x * blockDim.x;
    for (int i = blockIdx.x * blockDim.x + threadIdx.x; i < n4; i += stride) {
        float4 a = w[i], b = msk[i];
        float4 o;
        o.x = tf32_rna(a.x * b.x); o.y = tf32_rna(a.y * b.y);
        o.z = tf32_rna(a.z * b.z); o.w = tf32_rna(a.w * b.w);
        wm[i] = o;
    }
}

// ---------------- TF32 mma.sync GEMM: y = X * Wm^T + bias ----------------
// A = raw x (tf32 RNA applied in-register after ldmatrix), B = pre-rounded Wm.
// SMEM rows are 32 floats (128B), 16B-chunk XOR swizzle. Because the step index
// contributes bits [5:6] of the chunk field disjointly from the ldmatrix lane
// bit, the swizzled address factors as  addr(s) = base ^ (s << 5).
// Fragments are double-buffered (buf = s&1): step s+1 LDSMs issue before step s
// MMAs; at the stage boundary the wait+barrier+prefetch happens BEFORE the last
// step's MMAs (which are register-only), hiding the post-barrier LDSM latency.
__global__ void __launch_bounds__(THREADS, 2)
gemm_kernel(const float* __restrict__ A,   // x    [M][K] raw fp32
            const float* __restrict__ B,   // g_wm [N][K] tf32-rounded
            const float* __restrict__ bias,
            float* __restrict__ out) {
    extern __shared__ char smem[];
    const uint32_t sbase = smem_u32(smem);
    const int tid  = threadIdx.x;
    const int lane = tid & 31;
    const int wid  = tid >> 5;
    const int wm   = wid & 3;   // warp m position (x32): 4
    const int wn   = wid >> 2;  // warp n position (x64): 2

    const int m0 = blockIdx.x * BM;
    const int n0 = blockIdx.y * BN;
    const float* gA = A + (size_t)m0 * KDIM;
    const float* gB = B + (size_t)n0 * KDIM;

    // -------- stage loader: 8 x 16B cp.async per thread --------
    auto load_stage = [&](int kt, int slot) {
        const uint32_t sA = sbase + slot * SLOT;
        const uint32_t sB = sA + ASTAGE;
        const int kof = kt * BK;
        #pragma unroll
        for (int i = 0; i < 4; i++) {                 // A: 1024 chunks
            int id = tid + THREADS * i;
            int r = id >> 3, c = id & 7;
            cp_async16(sA + r * 128 + ((c ^ (r & 7)) << 4),
                       gA + (size_t)r * KDIM + kof + c * 4);
        }
        #pragma unroll
        for (int i = 0; i < 4; i++) {                 // B: 1024 chunks
            int id = tid + THREADS * i;
            int r = id >> 3, c = id & 7;
            cp_async16(sB + r * 128 + ((c ^ (r & 7)) << 4),
                       gB + (size_t)r * KDIM + kof + c * 4);
        }
    };

    // -------- per-lane fragment base addresses (relative to stage base) --------
    uint32_t afB[2], bfB[4];
    #pragma unroll
    for (int mt = 0; mt < 2; mt++) {
        int r = wm * 32 + mt * 16 + (lane & 15);
        int b = lane >> 4, k = r & 7;
        afB[mt] = r * 128 + (((b ^ (k & 1)) | (k & 6)) << 4);
    }
    #pragma unroll
    for (int p = 0; p < 4; p++) {
        int r = wn * 64 + p * 16 + (lane & 7) + ((lane >> 4) << 3);
        int b = (lane >> 3) & 1, k = r & 7;
        bfB[p] = r * 128 + (((b ^ (k & 1)) | (k & 6)) << 4);
    }

    uint32_t af[2][2][4], bf[2][8][2];   // double-buffered fragments

    auto ldfrag = [&](int buf, uint32_t stage_base, int s) {
        const uint32_t sA = stage_base;
        const uint32_t sB = stage_base + ASTAGE;
        const uint32_t sx = (uint32_t)(s << 5);
        #pragma unroll
        for (int mt = 0; mt < 2; mt++)
            ldsm_x4(af[buf][mt], sA + (afB[mt] ^ sx));
        #pragma unroll
        for (int p = 0; p < 4; p++) {
            uint32_t t[4];
            ldsm_x4(t, sB + (bfB[p] ^ sx));
            bf[buf][2 * p][0] = t[0];     bf[buf][2 * p][1] = t[1];
            bf[buf][2 * p + 1][0] = t[2]; bf[buf][2 * p + 1][1] = t[3];
        }
        // round A fragments (raw x) to tf32 RNA in-register
        #pragma unroll
        for (int mt = 0; mt < 2; mt++)
            #pragma unroll
            for (int i = 0; i < 4; i++)
                asm("cvt.rna.tf32.f32 %0, %0;" : "+r"(af[buf][mt][i]));
    };

    float acc[2][8][4];
    #pragma unroll
    for (int mt = 0; mt < 2; mt++)
        #pragma unroll
        for (int nt = 0; nt < 8; nt++)
            #pragma unroll
            for (int i = 0; i < 4; i++) acc[mt][nt][i] = 0.0f;

    // -------- prologue: stages 0,1 in flight; frags for (stage0, s0) --------
    load_stage(0, 0); cp_commit();
    load_stage(1, 1); cp_commit();
    cp_wait<1>();          // stage 0 complete (own-thread)
    __syncthreads();       // all threads' stage-0 writes visible
    ldfrag(0, sbase, 0);

    int slotC = 0, slotN = 1, slotL = 2;   // current / next / load-target slots

    // -------- main K loop --------
    for (int kt = 0; kt < KITERS; kt++) {
        // fill the slot freed at the end of kt-1 (barrier at kt-1 s=3 ordered it)
        if (kt + 2 < KITERS) load_stage(kt + 2, slotL);
        cp_commit();  // always commit to keep group accounting uniform

        const uint32_t stCur = sbase + slotC * SLOT;
        const uint32_t stNxt = sbase + slotN * SLOT;

        #pragma unroll
        for (int s = 0; s < 4; s++) {
            const int cur = s & 1, nxt = cur ^ 1;
            if (s < 3) {
                ldfrag(nxt, stCur, s + 1);
            } else if (kt + 1 < KITERS) {
                cp_wait<1>();      // stage kt+1 complete (own-thread)
                __syncthreads();   // visibility + frees slotC for overwrite next kt
                ldfrag(nxt, stNxt, 0);
            }
            #pragma unroll
            for (int mt = 0; mt < 2; mt++)
                #pragma unroll
                for (int nt = 0; nt < 8; nt++)
                    mma_tf32(acc[mt][nt], af[cur][mt], bf[cur][nt]);
        }
        int t = slotC; slotC = slotN; slotN = slotL; slotL = t;
    }
    cp_wait<0>();  // drain tail groups before exit

    // -------- epilogue: bias add + float2 stores --------
    const int r  = lane >> 2;
    const int c2 = (lane & 3) * 2;
    const float* bp = bias + n0 + wn * 64;
    float* op = out + (size_t)(m0 + wm * 32) * NDIM + n0 + wn * 64;

    #pragma unroll
    for (int mt = 0; mt < 2; mt++) {
        #pragma unroll
        for (int nt = 0; nt < 8; nt++) {
            int n = nt * 8 + c2;
            float b0 = __ldg(bp + n), b1 = __ldg(bp + n + 1);
            float2 v0 = {acc[mt][nt][0] + b0, acc[mt][nt][1] + b1};
            float2 v1 = {acc[mt][nt][2] + b0, acc[mt][nt][3] + b1};
            *reinterpret_cast<float2*>(op + (size_t)(mt * 16 + r) * NDIM + n) = v0;
            *reinterpret_cast<float2*>(op + (size_t)(mt * 16 + r + 8) * NDIM + n) = v1;
        }
    }
}

// ---------------- host ----------------
extern "C" void kernel_launch(void* const* d_in, const int* in_sizes, int n_in,
                              void* d_out, int out_size) {
    const float* x    = (const float*)d_in[0];
    const float* w    = (const float*)d_in[1];
    const float* bias = (const float*)d_in[2];
    const float* msk  = (const float*)d_in[3];
    float* out = (float*)d_out;

    void* wm_ptr = nullptr;
    cudaGetSymbolAddress(&wm_ptr, g_wm);

    // prep: W*M with tf32 RNA rounding (x is rounded in-register inside the GEMM)
    int n4 = (KDIM * NDIM) / 4;
    prep_kernel<<<4096, 256>>>((const float4*)w, (const float4*)msk,
                               (float4*)wm_ptr, n4);

    cudaFuncSetAttribute(gemm_kernel, cudaFuncAttributeMaxDynamicSharedMemorySize,
                         (int)SMEM_TOTAL);

    // m fastest in blockIdx.x: each ~296-CTA wave covers all 32 m-tiles for ~9 n-tiles,
    // keeping the 64MB x matrix L2-resident across the kernel.
    dim3 grid(MDIM / BM, NDIM / BN, 1);  // (32, 32)
    gemm_kernel<<<grid, THREADS, SMEM_TOTAL>>>(x, (const float*)wm_ptr, bias, out);
}

// round 9
// speedup vs baseline: 1.0616x; 1.0616x over previous
#include <cuda_runtime.h>
#include <cstdint>

// ---------------- problem constants ----------------
static constexpr int MDIM = 4096;   // batch
static constexpr int NDIM = 4096;   // out features
static constexpr int KDIM = 4096;   // in features

static constexpr int BM = 128;
static constexpr int BN = 128;
static constexpr int BK = 32;
static constexpr int THREADS = 256;          // 8 warps: 4 (m) x 2 (n), warp tile 32x64
static constexpr int KITERS  = KDIM / BK;    // 128

static constexpr uint32_t ASTAGE = BM * BK * 4;            // 16 KB
static constexpr uint32_t BSTAGE = BN * BK * 4;            // 16 KB
static constexpr uint32_t SLOT   = ASTAGE + BSTAGE;        // 32 KB
static constexpr uint32_t SMEM_TOTAL = 3 * SLOT;           // 96 KB -> 2 CTAs/SM

// ---------------- scratch (device globals: allocations are banned) ----------------
__device__ __align__(1024) float g_wm[(size_t)NDIM * KDIM];  // tf32-rounded masked weight
__device__ __align__(1024) float g_xr[(size_t)MDIM * KDIM];  // tf32-rounded x

// ---------------- sm_80-safe PTX helpers ----------------
__device__ __forceinline__ uint32_t smem_u32(const void* p) {
    uint32_t a;
    asm("{ .reg .u64 t; cvta.to.shared.u64 t, %1; cvt.u32.u64 %0, t; }" : "=r"(a) : "l"(p));
    return a;
}
__device__ __forceinline__ void cp_async16(uint32_t dst, const void* src) {
    asm volatile("cp.async.cg.shared.global [%0], [%1], 16;" :: "r"(dst), "l"(src) : "memory");
}
__device__ __forceinline__ void cp_commit() {
    asm volatile("cp.async.commit_group;" ::: "memory");
}
template <int N>
__device__ __forceinline__ void cp_wait() {
    asm volatile("cp.async.wait_group %0;" :: "n"(N) : "memory");
}
__device__ __forceinline__ void ldsm_x4(uint32_t* r, uint32_t addr) {
    asm volatile("ldmatrix.sync.aligned.m8n8.x4.shared.b16 {%0,%1,%2,%3}, [%4];"
                 : "=r"(r[0]), "=r"(r[1]), "=r"(r[2]), "=r"(r[3]) : "r"(addr));
}
__device__ __forceinline__ void mma_tf32(float* c, const uint32_t* a, const uint32_t* b) {
    asm volatile(
        "mma.sync.aligned.m16n8k8.row.col.f32.tf32.tf32.f32 "
        "{%0,%1,%2,%3}, {%4,%5,%6,%7}, {%8,%9}, {%0,%1,%2,%3};"
        : "+f"(c[0]), "+f"(c[1]), "+f"(c[2]), "+f"(c[3])
        : "r"(a[0]), "r"(a[1]), "r"(a[2]), "r"(a[3]), "r"(b[0]), "r"(b[1]));
}
__device__ __forceinline__ float tf32_rna(float f) {
    uint32_t o, i = __float_as_uint(f);
    asm("cvt.rna.tf32.f32 %0, %1;" : "=r"(o) : "r"(i));
    return __uint_as_float(o);
}

// ---------------- prep: masked weight + tf32 RNA rounding of both operands ----------------
__global__ void prep_kernel(const float4* __restrict__ w, const float4* __restrict__ msk,
                            const float4* __restrict__ x, float4* __restrict__ wm,
                            float4* __restrict__ xr, int n4) {
    int stride = gridDim.x * blockDim.x;
    for (int i = blockIdx.x * blockDim.x + threadIdx.x; i < n4; i += stride) {
        float4 a = w[i], b = msk[i];
        float4 o;
        o.x = tf32_rna(a.x * b.x); o.y = tf32_rna(a.y * b.y);
        o.z = tf32_rna(a.z * b.z); o.w = tf32_rna(a.w * b.w);
        wm[i] = o;
        float4 c = x[i];
        float4 p;
        p.x = tf32_rna(c.x); p.y = tf32_rna(c.y);
        p.z = tf32_rna(c.z); p.w = tf32_rna(c.w);
        xr[i] = p;
    }
}

// ---------------- TF32 mma.sync GEMM: y = Xr * Wm^T + bias ----------------
// SMEM rows: 32 floats (128B), 16B-chunk XOR swizzle. The k8-step index occupies
// address bits [5:6] disjointly from the ldmatrix lane bit, so the swizzled
// address factors as  addr(s) = base ^ (s << 5)  (verified: R8 passed with it).
// Fragments double-buffered (buf = s&1). At the stage boundary (s=3) the
// wait + __syncthreads + next-stage s0 LDSMs are issued BEFORE the s=3 MMA
// batch, whose register-only HMMAs then hide the post-barrier LDSM latency.
__global__ void __launch_bounds__(THREADS, 2)
gemm_kernel(const float* __restrict__ A,   // g_xr [M][K] tf32-rounded
            const float* __restrict__ B,   // g_wm [N][K] tf32-rounded
            const float* __restrict__ bias,
            float* __restrict__ out) {
    extern __shared__ char smem[];
    const uint32_t sbase = smem_u32(smem);
    const int tid  = threadIdx.x;
    const int lane = tid & 31;
    const int wid  = tid >> 5;
    const int wm   = wid & 3;   // warp m position (x32): 4
    const int wn   = wid >> 2;  // warp n position (x64): 2

    const int m0 = blockIdx.x * BM;
    const int n0 = blockIdx.y * BN;
    const float* gA = A + (size_t)m0 * KDIM;
    const float* gB = B + (size_t)n0 * KDIM;

    // -------- stage loader: 8 x 16B cp.async per thread --------
    auto load_stage = [&](int kt, uint32_t st) {
        const int kof = kt * BK;
        #pragma unroll
        for (int i = 0; i < 4; i++) {                 // A: 1024 chunks
            int id = tid + THREADS * i;
            int r = id >> 3, c = id & 7;
            cp_async16(st + r * 128 + ((c ^ (r & 7)) << 4),
                       gA + (size_t)r * KDIM + kof + c * 4);
        }
        #pragma unroll
        for (int i = 0; i < 4; i++) {                 // B: 1024 chunks
            int id = tid + THREADS * i;
            int r = id >> 3, c = id & 7;
            cp_async16(st + ASTAGE + r * 128 + ((c ^ (r & 7)) << 4),
                       gB + (size_t)r * KDIM + kof + c * 4);
        }
    };

    // -------- per-lane fragment base addresses (relative to stage base) --------
    uint32_t afB[2], bfB[4];
    #pragma unroll
    for (int mt = 0; mt < 2; mt++) {
        int r = wm * 32 + mt * 16 + (lane & 15);
        int b = lane >> 4, k = r & 7;
        afB[mt] = r * 128 + (((b ^ (k & 1)) | (k & 6)) << 4);
    }
    #pragma unroll
    for (int p = 0; p < 4; p++) {
        int r = wn * 64 + p * 16 + (lane & 7) + ((lane >> 4) << 3);
        int b = (lane >> 3) & 1, k = r & 7;
        bfB[p] = (ASTAGE + r * 128) + (((b ^ (k & 1)) | (k & 6)) << 4);
    }

    // double-buffered fragments; B LDSM lands directly in final registers
    uint32_t af[2][2][4], bf[2][4][4];

    auto ldfrag = [&](int buf, uint32_t st, int s) {
        const uint32_t sx = (uint32_t)(s << 5);
        #pragma unroll
        for (int mt = 0; mt < 2; mt++)
            ldsm_x4(af[buf][mt], st + (afB[mt] ^ sx));
        #pragma unroll
        for (int p = 0; p < 4; p++)
            ldsm_x4(bf[buf][p], st + (bfB[p] ^ sx));
    };

    float acc[2][8][4];
    #pragma unroll
    for (int mt = 0; mt < 2; mt++)
        #pragma unroll
        for (int nt = 0; nt < 8; nt++)
            #pragma unroll
            for (int i = 0; i < 4; i++) acc[mt][nt][i] = 0.0f;

    auto mma_step = [&](int buf) {
        #pragma unroll
        for (int mt = 0; mt < 2; mt++)
            #pragma unroll
            for (int nt = 0; nt < 8; nt++)
                mma_tf32(acc[mt][nt], af[buf][mt], &bf[buf][nt >> 1][2 * (nt & 1)]);
    };

    // -------- prologue: stages 0,1 in flight; frags for (stage0, s0) --------
    uint32_t stC = sbase, stN = sbase + SLOT, stL = sbase + 2 * SLOT;
    load_stage(0, stC); cp_commit();
    load_stage(1, stN); cp_commit();
    cp_wait<1>();          // own stage-0 group done
    __syncthreads();       // all threads' stage-0 writes visible
    ldfrag(0, stC, 0);

    // -------- main K loop --------
    for (int kt = 0; kt < KITERS; kt++) {
        // slot stL was freed by the barrier inside kt-1; prefetch kt+2 into it
        if (kt + 2 < KITERS) load_stage(kt + 2, stL);
        cp_commit();  // always commit to keep group accounting uniform

        ldfrag(1, stC, 1);  mma_step(0);   // s=0
        ldfrag(0, stC, 2);  mma_step(1);   // s=1
        ldfrag(1, stC, 3);  mma_step(0);   // s=2
        if (kt + 1 < KITERS) {             // s=3: boundary reorder
            cp_wait<1>();      // stage kt+1 landed (kt+2 group still pending)
            __syncthreads();   // visibility; also frees stC for the kt+1 prefetch
            ldfrag(0, stN, 0);
        }
        mma_step(1);

        uint32_t t = stC; stC = stN; stN = stL; stL = t;
    }
    cp_wait<0>();  // drain tail groups before exit

    // -------- epilogue: bias add + float2 stores --------
    const int r  = lane >> 2;
    const int c2 = (lane & 3) * 2;
    const float* bp = bias + n0 + wn * 64;
    float* op = out + (size_t)(m0 + wm * 32) * NDIM + n0 + wn * 64;

    #pragma unroll
    for (int mt = 0; mt < 2; mt++) {
        #pragma unroll
        for (int nt = 0; nt < 8; nt++) {
            int n = nt * 8 + c2;
            float b0 = __ldg(bp + n), b1 = __ldg(bp + n + 1);
            float2 v0 = {acc[mt][nt][0] + b0, acc[mt][nt][1] + b1};
            float2 v1 = {acc[mt][nt][2] + b0, acc[mt][nt][3] + b1};
            *reinterpret_cast<float2*>(op + (size_t)(mt * 16 + r) * NDIM + n) = v0;
            *reinterpret_cast<float2*>(op + (size_t)(mt * 16 + r + 8) * NDIM + n) = v1;
        }
    }
}

// ---------------- host ----------------
extern "C" void kernel_launch(void* const* d_in, const int* in_sizes, int n_in,
                              void* d_out, int out_size) {
    const float* x    = (const float*)d_in[0];
    const float* w    = (const float*)d_in[1];
    const float* bias = (const float*)d_in[2];
    const float* msk  = (const float*)d_in[3];
    float* out = (float*)d_out;

    void* wm_ptr = nullptr;
    void* xr_ptr = nullptr;
    cudaGetSymbolAddress(&wm_ptr, g_wm);
    cudaGetSymbolAddress(&xr_ptr, g_xr);

    // prep: W*M and x, both tf32 RNA pre-rounded (keeps the GEMM loop cvt-free)
    int n4 = (KDIM * NDIM) / 4;
    prep_kernel<<<4096, 256>>>((const float4*)w, (const float4*)msk, (const float4*)x,
                               (float4*)wm_ptr, (float4*)xr_ptr, n4);

    cudaFuncSetAttribute(gemm_kernel, cudaFuncAttributeMaxDynamicSharedMemorySize,
                         (int)SMEM_TOTAL);

    // m fastest in blockIdx.x: each ~296-CTA wave covers all 32 m-tiles for ~9 n-tiles,
    // keeping the 64MB x matrix + active B panels L2-resident (DRAM was 10%).
    dim3 grid(MDIM / BM, NDIM / BN, 1);  // (32, 32)
    gemm_kernel<<<grid, THREADS, SMEM_TOTAL>>>((const float*)xr_ptr, (const float*)wm_ptr,
                                               bias, out);
}

// round 10
// speedup vs baseline: 2.2291x; 2.0998x over previous
#include <cuda_runtime.h>
#include <cuda_fp16.h>
#include <cstdint>

// ---------------- problem constants ----------------
static constexpr int MDIM = 4096;   // batch
static constexpr int NDIM = 4096;   // out features
static constexpr int KDIM = 4096;   // in features

static constexpr int BM = 128;
static constexpr int BN = 128;
static constexpr int BK = 64;                // halves per stage (128B rows)
static constexpr int THREADS = 256;          // 8 warps: 4 (m) x 2 (n), warp tile 32x64
static constexpr int KITERS  = KDIM / BK;    // 64

static constexpr uint32_t ASTAGE = BM * BK * 2;            // 16 KB
static constexpr uint32_t BSTAGE = BN * BK * 2;            // 16 KB
static constexpr uint32_t SLOT   = ASTAGE + BSTAGE;        // 32 KB
static constexpr uint32_t SMEM_TOTAL = 3 * SLOT;           // 96 KB -> 2 CTAs/SM

// ---------------- scratch (device globals: allocations are banned) ----------------
__device__ __align__(1024) __half g_wm[(size_t)NDIM * KDIM];  // fp16 masked weight
__device__ __align__(1024) __half g_xr[(size_t)MDIM * KDIM];  // fp16 x

// ---------------- sm_80-safe PTX helpers ----------------
__device__ __forceinline__ uint32_t smem_u32(const void* p) {
    uint32_t a;
    asm("{ .reg .u64 t; cvta.to.shared.u64 t, %1; cvt.u32.u64 %0, t; }" : "=r"(a) : "l"(p));
    return a;
}
__device__ __forceinline__ void cp_async16(uint32_t dst, const void* src) {
    asm volatile("cp.async.cg.shared.global [%0], [%1], 16;" :: "r"(dst), "l"(src) : "memory");
}
__device__ __forceinline__ void cp_commit() {
    asm volatile("cp.async.commit_group;" ::: "memory");
}
template <int N>
__device__ __forceinline__ void cp_wait() {
    asm volatile("cp.async.wait_group %0;" :: "n"(N) : "memory");
}
__device__ __forceinline__ void ldsm_x4(uint32_t* r, uint32_t addr) {
    asm volatile("ldmatrix.sync.aligned.m8n8.x4.shared.b16 {%0,%1,%2,%3}, [%4];"
                 : "=r"(r[0]), "=r"(r[1]), "=r"(r[2]), "=r"(r[3]) : "r"(addr));
}
__device__ __forceinline__ void mma_f16(float* c, const uint32_t* a, const uint32_t* b) {
    asm volatile(
        "mma.sync.aligned.m16n8k16.row.col.f32.f16.f16.f32 "
        "{%0,%1,%2,%3}, {%4,%5,%6,%7}, {%8,%9}, {%0,%1,%2,%3};"
        : "+f"(c[0]), "+f"(c[1]), "+f"(c[2]), "+f"(c[3])
        : "r"(a[0]), "r"(a[1]), "r"(a[2]), "r"(a[3]), "r"(b[0]), "r"(b[1]));
}

// ---------------- prep: masked weight + x, both converted to fp16 RN ----------------
__global__ void prep_kernel(const float4* __restrict__ w, const float4* __restrict__ msk,
                            const float4* __restrict__ x, uint2* __restrict__ wm,
                            uint2* __restrict__ xr, int n4) {
    int stride = gridDim.x * blockDim.x;
    for (int i = blockIdx.x * blockDim.x + threadIdx.x; i < n4; i += stride) {
        float4 a = w[i], b = msk[i];
        __half2 lo = __floats2half2_rn(a.x * b.x, a.y * b.y);
        __half2 hi = __floats2half2_rn(a.z * b.z, a.w * b.w);
        uint2 o;
        o.x = *reinterpret_cast<uint32_t*>(&lo);
        o.y = *reinterpret_cast<uint32_t*>(&hi);
        wm[i] = o;
        float4 c = x[i];
        __half2 l2 = __floats2half2_rn(c.x, c.y);
        __half2 h2 = __floats2half2_rn(c.z, c.w);
        uint2 p;
        p.x = *reinterpret_cast<uint32_t*>(&l2);
        p.y = *reinterpret_cast<uint32_t*>(&h2);
        xr[i] = p;
    }
}

// ---------------- fp16 mma.sync GEMM: y = Xh * Wmh^T + bias (fp32 accum) ----------------
// R7's proven structure (inline per-step ldmatrix + mma, compiler-scheduled),
// retyped to fp16: rows are 64 halves = 128B, 16B-chunk XOR swizzle, k16 steps.
// The step index occupies chunk bits 1-2 (byte bits 5-6) disjointly from the
// ldmatrix chunk-select bit, so the swizzled address factors as base ^ (s<<5).
__global__ void __launch_bounds__(THREADS, 2)
gemm_kernel(const __half* __restrict__ A,   // g_xr [M][K] fp16
            const __half* __restrict__ B,   // g_wm [N][K] fp16
            const float* __restrict__ bias,
            float* __restrict__ out) {
    extern __shared__ char smem[];
    const uint32_t sbase = smem_u32(smem);
    const int tid  = threadIdx.x;
    const int lane = tid & 31;
    const int wid  = tid >> 5;
    const int wm   = wid & 3;   // warp m position (x32): 4
    const int wn   = wid >> 2;  // warp n position (x64): 2

    const int m0 = blockIdx.x * BM;
    const int n0 = blockIdx.y * BN;
    const __half* gA = A + (size_t)m0 * KDIM;
    const __half* gB = B + (size_t)n0 * KDIM;

    // -------- stage loader: 8 x 16B cp.async per thread --------
    auto load_stage = [&](int kt, uint32_t st) {
        const int kof = kt * BK;
        #pragma unroll
        for (int i = 0; i < 4; i++) {                 // A: 1024 chunks (128 rows x 8)
            int id = tid + THREADS * i;
            int r = id >> 3, c = id & 7;
            cp_async16(st + r * 128 + ((c ^ (r & 7)) << 4),
                       gA + (size_t)r * KDIM + kof + c * 8);
        }
        #pragma unroll
        for (int i = 0; i < 4; i++) {                 // B: 1024 chunks
            int id = tid + THREADS * i;
            int r = id >> 3, c = id & 7;
            cp_async16(st + ASTAGE + r * 128 + ((c ^ (r & 7)) << 4),
                       gB + (size_t)r * KDIM + kof + c * 8);
        }
    };

    // -------- per-lane fragment base addresses (relative to stage base) --------
    uint32_t afB[2], bfB[4];
    #pragma unroll
    for (int mt = 0; mt < 2; mt++) {
        int r = wm * 32 + mt * 16 + (lane & 15);
        int b = lane >> 4, k = r & 7;
        afB[mt] = r * 128 + (((b ^ (k & 1)) | (k & 6)) << 4);
    }
    #pragma unroll
    for (int p = 0; p < 4; p++) {
        int r = wn * 64 + p * 16 + (lane & 7) + ((lane >> 4) << 3);
        int b = (lane >> 3) & 1, k = r & 7;
        bfB[p] = (ASTAGE + r * 128) + (((b ^ (k & 1)) | (k & 6)) << 4);
    }

    float acc[2][8][4];
    #pragma unroll
    for (int mt = 0; mt < 2; mt++)
        #pragma unroll
        for (int nt = 0; nt < 8; nt++)
            #pragma unroll
            for (int i = 0; i < 4; i++) acc[mt][nt][i] = 0.0f;

    // -------- prologue: stages 0,1 in flight --------
    uint32_t stC = sbase, stN = sbase + SLOT, stL = sbase + 2 * SLOT;
    load_stage(0, stC); cp_commit();
    load_stage(1, stN); cp_commit();
    cp_wait<1>();
    __syncthreads();

    // -------- main K loop --------
    for (int kt = 0; kt < KITERS; kt++) {
        if (kt + 2 < KITERS) load_stage(kt + 2, stL);
        cp_commit();  // always commit to keep group accounting uniform

        #pragma unroll
        for (int s = 0; s < 4; s++) {                 // 4 k16 steps
            const uint32_t sx = (uint32_t)(s << 5);
            uint32_t af[2][4], bf[8][2];
            #pragma unroll
            for (int mt = 0; mt < 2; mt++)
                ldsm_x4(af[mt], stC + (afB[mt] ^ sx));
            #pragma unroll
            for (int p = 0; p < 4; p++) {
                uint32_t t[4];
                ldsm_x4(t, stC + (bfB[p] ^ sx));
                bf[2 * p][0] = t[0];     bf[2 * p][1] = t[1];
                bf[2 * p + 1][0] = t[2]; bf[2 * p + 1][1] = t[3];
            }
            #pragma unroll
            for (int mt = 0; mt < 2; mt++)
                #pragma unroll
                for (int nt = 0; nt < 8; nt++)
                    mma_f16(acc[mt][nt], af[mt], bf[nt]);
        }

        cp_wait<1>();      // next stage landed (prefetch group still pending)
        __syncthreads();   // visibility; frees stC for reuse as load target
        uint32_t t = stC; stC = stN; stN = stL; stL = t;
    }
    cp_wait<0>();  // drain tail groups before exit

    // -------- epilogue: bias add + float2 stores --------
    const int r  = lane >> 2;
    const int c2 = (lane & 3) * 2;
    const float* bp = bias + n0 + wn * 64;
    float* op = out + (size_t)(m0 + wm * 32) * NDIM + n0 + wn * 64;

    #pragma unroll
    for (int mt = 0; mt < 2; mt++) {
        #pragma unroll
        for (int nt = 0; nt < 8; nt++) {
            int n = nt * 8 + c2;
            float b0 = __ldg(bp + n), b1 = __ldg(bp + n + 1);
            float2 v0 = {acc[mt][nt][0] + b0, acc[mt][nt][1] + b1};
            float2 v1 = {acc[mt][nt][2] + b0, acc[mt][nt][3] + b1};
            *reinterpret_cast<float2*>(op + (size_t)(mt * 16 + r) * NDIM + n) = v0;
            *reinterpret_cast<float2*>(op + (size_t)(mt * 16 + r + 8) * NDIM + n) = v1;
        }
    }
}

// ---------------- host ----------------
extern "C" void kernel_launch(void* const* d_in, const int* in_sizes, int n_in,
                              void* d_out, int out_size) {
    const float* x    = (const float*)d_in[0];
    const float* w    = (const float*)d_in[1];
    const float* bias = (const float*)d_in[2];
    const float* msk  = (const float*)d_in[3];
    float* out = (float*)d_out;

    void* wm_ptr = nullptr;
    void* xr_ptr = nullptr;
    cudaGetSymbolAddress(&wm_ptr, g_wm);
    cudaGetSymbolAddress(&xr_ptr, g_xr);

    // prep: W*M and x converted to fp16 (same 11-bit mantissa as the tf32 path)
    int n4 = (KDIM * NDIM) / 4;
    prep_kernel<<<4096, 256>>>((const float4*)w, (const float4*)msk, (const float4*)x,
                               (uint2*)wm_ptr, (uint2*)xr_ptr, n4);

    cudaFuncSetAttribute(gemm_kernel, cudaFuncAttributeMaxDynamicSharedMemorySize,
                         (int)SMEM_TOTAL);

    // m fastest in blockIdx.x: each ~296-CTA wave covers all 32 m-tiles for ~9 n-tiles,
    // keeping the 32MB fp16 x matrix + active B panels L2-resident.
    dim3 grid(MDIM / BM, NDIM / BN, 1);  // (32, 32)
    gemm_kernel<<<grid, THREADS, SMEM_TOTAL>>>((const __half*)xr_ptr, (const __half*)wm_ptr,
                                               bias, out);
}

// round 11
// speedup vs baseline: 2.2304x; 1.0006x over previous
#include <cuda_runtime.h>
#include <cuda_fp16.h>
#include <cstdint>

// ---------------- problem constants ----------------
static constexpr int MDIM = 4096;   // batch
static constexpr int NDIM = 4096;   // out features
static constexpr int KDIM = 4096;   // in features

static constexpr int BM = 128;
static constexpr int BN = 128;
static constexpr int BK = 64;                // halves per stage (128B rows)
static constexpr int THREADS = 256;          // 8 warps: 4 (m) x 2 (n), warp tile 32x64
static constexpr int KITERS  = KDIM / BK;    // 64

static constexpr uint32_t ASTAGE = BM * BK * 2;            // 16 KB
static constexpr uint32_t BSTAGE = BN * BK * 2;            // 16 KB
static constexpr uint32_t SLOT   = ASTAGE + BSTAGE;        // 32 KB
static constexpr uint32_t SMEM_TOTAL = 3 * SLOT;           // 96 KB -> 2 CTAs/SM

// ---------------- scratch (device globals: allocations are banned) ----------------
__device__ __align__(1024) __half g_wm[(size_t)NDIM * KDIM];  // fp16 masked weight
__device__ __align__(1024) __half g_xr[(size_t)MDIM * KDIM];  // fp16 x

// ---------------- sm_80-safe PTX helpers ----------------
__device__ __forceinline__ uint32_t smem_u32(const void* p) {
    uint32_t a;
    asm("{ .reg .u64 t; cvta.to.shared.u64 t, %1; cvt.u32.u64 %0, t; }" : "=r"(a) : "l"(p));
    return a;
}
__device__ __forceinline__ void cp_async16(uint32_t dst, const void* src) {
    asm volatile("cp.async.cg.shared.global [%0], [%1], 16;" :: "r"(dst), "l"(src) : "memory");
}
__device__ __forceinline__ void cp_commit() {
    asm volatile("cp.async.commit_group;" ::: "memory");
}
template <int N>
__device__ __forceinline__ void cp_wait() {
    asm volatile("cp.async.wait_group %0;" :: "n"(N) : "memory");
}
__device__ __forceinline__ void ldsm_x4(uint32_t* r, uint32_t addr) {
    asm volatile("ldmatrix.sync.aligned.m8n8.x4.shared.b16 {%0,%1,%2,%3}, [%4];"
                 : "=r"(r[0]), "=r"(r[1]), "=r"(r[2]), "=r"(r[3]) : "r"(addr));
}
__device__ __forceinline__ void mma_f16(float* c, const uint32_t* a, const uint32_t* b) {
    asm volatile(
        "mma.sync.aligned.m16n8k16.row.col.f32.f16.f16.f32 "
        "{%0,%1,%2,%3}, {%4,%5,%6,%7}, {%8,%9}, {%0,%1,%2,%3};"
        : "+f"(c[0]), "+f"(c[1]), "+f"(c[2]), "+f"(c[3])
        : "r"(a[0]), "r"(a[1]), "r"(a[2]), "r"(a[3]), "r"(b[0]), "r"(b[1]));
}

// ---------------- prep: masked weight + x, both converted to fp16 RN ----------------
__global__ void prep_kernel(const float4* __restrict__ w, const float4* __restrict__ msk,
                            const float4* __restrict__ x, uint2* __restrict__ wm,
                            uint2* __restrict__ xr, int n4) {
    int stride = gridDim.x * blockDim.x;
    for (int i = blockIdx.x * blockDim.x + threadIdx.x; i < n4; i += stride) {
        float4 a = w[i], b = msk[i];
        __half2 lo = __floats2half2_rn(a.x * b.x, a.y * b.y);
        __half2 hi = __floats2half2_rn(a.z * b.z, a.w * b.w);
        uint2 o;
        o.x = *reinterpret_cast<uint32_t*>(&lo);
        o.y = *reinterpret_cast<uint32_t*>(&hi);
        wm[i] = o;
        float4 c = x[i];
        __half2 l2 = __floats2half2_rn(c.x, c.y);
        __half2 h2 = __floats2half2_rn(c.z, c.w);
        uint2 p;
        p.x = *reinterpret_cast<uint32_t*>(&l2);
        p.y = *reinterpret_cast<uint32_t*>(&h2);
        xr[i] = p;
    }
}

// ---------------- fp16 mma.sync GEMM: y = Xh * Wmh^T + bias (fp32 accum) ----------------
// R10 structure with one change: the stage-boundary barrier is hoisted between
// step s=3's LDSMs and its MMAs. The s=3 fragments are register-resident across
// the barrier (the in-flight prefetch targets stL, never stC), so after the
// barrier each warp issues 16 register-only HMMAs whose execution covers the
// next stage's s=0 LDSM latency — previously fully exposed. Zero extra live
// fragment sets (the R8/R9 register-pressure failure mode is avoided).
__global__ void __launch_bounds__(THREADS, 2)
gemm_kernel(const __half* __restrict__ A,   // g_xr [M][K] fp16
            const __half* __restrict__ B,   // g_wm [N][K] fp16
            const float* __restrict__ bias,
            float* __restrict__ out) {
    extern __shared__ char smem[];
    const uint32_t sbase = smem_u32(smem);
    const int tid  = threadIdx.x;
    const int lane = tid & 31;
    const int wid  = tid >> 5;
    const int wm   = wid & 3;   // warp m position (x32): 4
    const int wn   = wid >> 2;  // warp n position (x64): 2

    const int m0 = blockIdx.x * BM;
    const int n0 = blockIdx.y * BN;
    const __half* gA = A + (size_t)m0 * KDIM;
    const __half* gB = B + (size_t)n0 * KDIM;

    // -------- stage loader: 8 x 16B cp.async per thread --------
    auto load_stage = [&](int kt, uint32_t st) {
        const int kof = kt * BK;
        #pragma unroll
        for (int i = 0; i < 4; i++) {                 // A: 1024 chunks (128 rows x 8)
            int id = tid + THREADS * i;
            int r = id >> 3, c = id & 7;
            cp_async16(st + r * 128 + ((c ^ (r & 7)) << 4),
                       gA + (size_t)r * KDIM + kof + c * 8);
        }
        #pragma unroll
        for (int i = 0; i < 4; i++) {                 // B: 1024 chunks
            int id = tid + THREADS * i;
            int r = id >> 3, c = id & 7;
            cp_async16(st + ASTAGE + r * 128 + ((c ^ (r & 7)) << 4),
                       gB + (size_t)r * KDIM + kof + c * 8);
        }
    };

    // -------- per-lane fragment base addresses (relative to stage base) --------
    uint32_t afB[2], bfB[4];
    #pragma unroll
    for (int mt = 0; mt < 2; mt++) {
        int r = wm * 32 + mt * 16 + (lane & 15);
        int b = lane >> 4, k = r & 7;
        afB[mt] = r * 128 + (((b ^ (k & 1)) | (k & 6)) << 4);
    }
    #pragma unroll
    for (int p = 0; p < 4; p++) {
        int r = wn * 64 + p * 16 + (lane & 7) + ((lane >> 4) << 3);
        int b = (lane >> 3) & 1, k = r & 7;
        bfB[p] = (ASTAGE + r * 128) + (((b ^ (k & 1)) | (k & 6)) << 4);
    }

    float acc[2][8][4];
    #pragma unroll
    for (int mt = 0; mt < 2; mt++)
        #pragma unroll
        for (int nt = 0; nt < 8; nt++)
            #pragma unroll
            for (int i = 0; i < 4; i++) acc[mt][nt][i] = 0.0f;

    // -------- prologue: stages 0,1 in flight --------
    uint32_t stC = sbase, stN = sbase + SLOT, stL = sbase + 2 * SLOT;
    load_stage(0, stC); cp_commit();
    load_stage(1, stN); cp_commit();
    cp_wait<1>();
    __syncthreads();

    // -------- main K loop --------
    for (int kt = 0; kt < KITERS; kt++) {
        if (kt + 2 < KITERS) load_stage(kt + 2, stL);
        cp_commit();  // always commit to keep group accounting uniform

        #pragma unroll
        for (int s = 0; s < 3; s++) {                 // k16 steps 0..2
            const uint32_t sx = (uint32_t)(s << 5);
            uint32_t af[2][4], bf[8][2];
            #pragma unroll
            for (int mt = 0; mt < 2; mt++)
                ldsm_x4(af[mt], stC + (afB[mt] ^ sx));
            #pragma unroll
            for (int p = 0; p < 4; p++) {
                uint32_t t[4];
                ldsm_x4(t, stC + (bfB[p] ^ sx));
                bf[2 * p][0] = t[0];     bf[2 * p][1] = t[1];
                bf[2 * p + 1][0] = t[2]; bf[2 * p + 1][1] = t[3];
            }
            #pragma unroll
            for (int mt = 0; mt < 2; mt++)
                #pragma unroll
                for (int nt = 0; nt < 8; nt++)
                    mma_f16(acc[mt][nt], af[mt], bf[nt]);
        }

        // ----- step s=3: LDSM, then barrier, then register-only MMAs -----
        {
            const uint32_t sx = 3u << 5;
            uint32_t af[2][4], bf[8][2];
            #pragma unroll
            for (int mt = 0; mt < 2; mt++)
                ldsm_x4(af[mt], stC + (afB[mt] ^ sx));
            #pragma unroll
            for (int p = 0; p < 4; p++) {
                uint32_t t[4];
                ldsm_x4(t, stC + (bfB[p] ^ sx));
                bf[2 * p][0] = t[0];     bf[2 * p][1] = t[1];
                bf[2 * p + 1][0] = t[2]; bf[2 * p + 1][1] = t[3];
            }
            cp_wait<1>();      // next stage landed (prefetch group still pending)
            __syncthreads();   // frees stC as next load target; frags live in regs
            #pragma unroll
            for (int mt = 0; mt < 2; mt++)
                #pragma unroll
                for (int nt = 0; nt < 8; nt++)
                    mma_f16(acc[mt][nt], af[mt], bf[nt]);
        }

        uint32_t t = stC; stC = stN; stN = stL; stL = t;
    }
    cp_wait<0>();  // drain tail groups before exit

    // -------- epilogue: bias add + float2 stores --------
    const int r  = lane >> 2;
    const int c2 = (lane & 3) * 2;
    const float* bp = bias + n0 + wn * 64;
    float* op = out + (size_t)(m0 + wm * 32) * NDIM + n0 + wn * 64;

    #pragma unroll
    for (int mt = 0; mt < 2; mt++) {
        #pragma unroll
        for (int nt = 0; nt < 8; nt++) {
            int n = nt * 8 + c2;
            float b0 = __ldg(bp + n), b1 = __ldg(bp + n + 1);
            float2 v0 = {acc[mt][nt][0] + b0, acc[mt][nt][1] + b1};
            float2 v1 = {acc[mt][nt][2] + b0, acc[mt][nt][3] + b1};
            *reinterpret_cast<float2*>(op + (size_t)(mt * 16 + r) * NDIM + n) = v0;
            *reinterpret_cast<float2*>(op + (size_t)(mt * 16 + r + 8) * NDIM + n) = v1;
        }
    }
}

// ---------------- host ----------------
extern "C" void kernel_launch(void* const* d_in, const int* in_sizes, int n_in,
                              void* d_out, int out_size) {
    const float* x    = (const float*)d_in[0];
    const float* w    = (const float*)d_in[1];
    const float* bias = (const float*)d_in[2];
    const float* msk  = (const float*)d_in[3];
    float* out = (float*)d_out;

    void* wm_ptr = nullptr;
    void* xr_ptr = nullptr;
    cudaGetSymbolAddress(&wm_ptr, g_wm);
    cudaGetSymbolAddress(&xr_ptr, g_xr);

    // prep: W*M and x converted to fp16 (same 11-bit mantissa as the tf32 path)
    int n4 = (KDIM * NDIM) / 4;
    prep_kernel<<<4096, 256>>>((const float4*)w, (const float4*)msk, (const float4*)x,
                               (uint2*)wm_ptr, (uint2*)xr_ptr, n4);

    cudaFuncSetAttribute(gemm_kernel, cudaFuncAttributeMaxDynamicSharedMemorySize,
                         (int)SMEM_TOTAL);

    // m fastest in blockIdx.x: each ~296-CTA wave covers all 32 m-tiles for ~9 n-tiles,
    // keeping the 32MB fp16 x matrix + active B panels L2-resident.
    dim3 grid(MDIM / BM, NDIM / BN, 1);  // (32, 32)
    gemm_kernel<<<grid, THREADS, SMEM_TOTAL>>>((const __half*)xr_ptr, (const __half*)wm_ptr,
                                               bias, out);
}

// round 12
// speedup vs baseline: 2.2306x; 1.0001x over previous
#include <cuda_runtime.h>
#include <cuda_fp16.h>
#include <cstdint>

// ---------------- problem constants ----------------
static constexpr int MDIM = 4096;   // batch
static constexpr int NDIM = 4096;   // out features
static constexpr int KDIM = 4096;   // in features

static constexpr int BM = 128;
static constexpr int BN = 128;
static constexpr int BK = 64;                // halves per stage (128B rows)
static constexpr int THREADS = 256;          // 8 warps: 4 (m) x 2 (n), warp tile 32x64
static constexpr int KITERS  = KDIM / BK;    // 64

static constexpr uint32_t ASTAGE = BM * BK * 2;            // 16 KB
static constexpr uint32_t BSTAGE = BN * BK * 2;            // 16 KB
static constexpr uint32_t SLOT   = ASTAGE + BSTAGE;        // 32 KB
static constexpr uint32_t SMEM_TOTAL = 3 * SLOT;           // 96 KB -> 2 CTAs/SM

// ---------------- scratch (device globals: allocations are banned) ----------------
__device__ __align__(1024) __half g_wm[(size_t)NDIM * KDIM];  // fp16 masked weight
__device__ __align__(1024) __half g_xr[(size_t)MDIM * KDIM];  // fp16 x

// ---------------- sm_80-safe PTX helpers ----------------
__device__ __forceinline__ uint32_t smem_u32(const void* p) {
    uint32_t a;
    asm("{ .reg .u64 t; cvta.to.shared.u64 t, %1; cvt.u32.u64 %0, t; }" : "=r"(a) : "l"(p));
    return a;
}
__device__ __forceinline__ void cp_async16(uint32_t dst, const void* src) {
    asm volatile("cp.async.cg.shared.global [%0], [%1], 16;" :: "r"(dst), "l"(src) : "memory");
}
__device__ __forceinline__ void cp_commit() {
    asm volatile("cp.async.commit_group;" ::: "memory");
}
template <int N>
__device__ __forceinline__ void cp_wait() {
    asm volatile("cp.async.wait_group %0;" :: "n"(N) : "memory");
}
// Named-barrier producer/consumer split: 256 arrives + 256 syncs = 512.
__device__ __forceinline__ void bar_arrive_1() {
    asm volatile("bar.arrive 1, 512;" ::: "memory");
}
__device__ __forceinline__ void bar_sync_1() {
    asm volatile("bar.sync 1, 512;" ::: "memory");
}
__device__ __forceinline__ void ldsm_x4(uint32_t* r, uint32_t addr) {
    asm volatile("ldmatrix.sync.aligned.m8n8.x4.shared.b16 {%0,%1,%2,%3}, [%4];"
                 : "=r"(r[0]), "=r"(r[1]), "=r"(r[2]), "=r"(r[3]) : "r"(addr));
}
__device__ __forceinline__ void mma_f16(float* c, const uint32_t* a, const uint32_t* b) {
    asm volatile(
        "mma.sync.aligned.m16n8k16.row.col.f32.f16.f16.f32 "
        "{%0,%1,%2,%3}, {%4,%5,%6,%7}, {%8,%9}, {%0,%1,%2,%3};"
        : "+f"(c[0]), "+f"(c[1]), "+f"(c[2]), "+f"(c[3])
        : "r"(a[0]), "r"(a[1]), "r"(a[2]), "r"(a[3]), "r"(b[0]), "r"(b[1]));
}

// ---------------- prep: masked weight + x, both converted to fp16 RN ----------------
__global__ void prep_kernel(const float4* __restrict__ w, const float4* __restrict__ msk,
                            const float4* __restrict__ x, uint2* __restrict__ wm,
                            uint2* __restrict__ xr, int n4) {
    int stride = gridDim.x * blockDim.x;
    for (int i = blockIdx.x * blockDim.x + threadIdx.x; i < n4; i += stride) {
        float4 a = w[i], b = msk[i];
        __half2 lo = __floats2half2_rn(a.x * b.x, a.y * b.y);
        __half2 hi = __floats2half2_rn(a.z * b.z, a.w * b.w);
        uint2 o;
        o.x = *reinterpret_cast<uint32_t*>(&lo);
        o.y = *reinterpret_cast<uint32_t*>(&hi);
        wm[i] = o;
        float4 c = x[i];
        __half2 l2 = __floats2half2_rn(c.x, c.y);
        __half2 h2 = __floats2half2_rn(c.z, c.w);
        uint2 p;
        p.x = *reinterpret_cast<uint32_t*>(&l2);
        p.y = *reinterpret_cast<uint32_t*>(&h2);
        xr[i] = p;
    }
}

// ---------------- fp16 mma.sync GEMM: y = Xh * Wmh^T + bias (fp32 accum) ----------------
// R11 structure with the per-kt __syncthreads replaced by a named-barrier
// arrive/sync split (PTX producer-consumer idiom, counts sum to 512):
//   ... s=3 LDSMs (last reads of stC) ... cp_wait<1> (my stage-kt+1 group done)
//   bar.arrive            <- non-blocking: publish reads-done + data-landed
//   ... s=3 MMAs (register-only) ...      <- useful work during others' skew
//   [next kt] bar.sync    <- blocks only here, right before stC is overwritten
// WAR safe: LDSM smem reads execute before the arrive issues; overwriting
// cp.asyncs issue only after sync release (all 256 arrives seen).
// RAW safe: every thread's cp_wait<1> precedes its arrive, so sync release
// publishes stage kt+1's data CTA-wide (cp.async wait + CTA barrier edge).
__global__ void __launch_bounds__(THREADS, 2)
gemm_kernel(const __half* __restrict__ A,   // g_xr [M][K] fp16
            const __half* __restrict__ B,   // g_wm [N][K] fp16
            const float* __restrict__ bias,
            float* __restrict__ out) {
    extern __shared__ char smem[];
    const uint32_t sbase = smem_u32(smem);
    const int tid  = threadIdx.x;
    const int lane = tid & 31;
    const int wid  = tid >> 5;
    const int wm   = wid & 3;   // warp m position (x32): 4
    const int wn   = wid >> 2;  // warp n position (x64): 2

    const int m0 = blockIdx.x * BM;
    const int n0 = blockIdx.y * BN;
    const __half* gA = A + (size_t)m0 * KDIM;
    const __half* gB = B + (size_t)n0 * KDIM;

    // -------- stage loader: 8 x 16B cp.async per thread --------
    auto load_stage = [&](int kt, uint32_t st) {
        const int kof = kt * BK;
        #pragma unroll
        for (int i = 0; i < 4; i++) {                 // A: 1024 chunks (128 rows x 8)
            int id = tid + THREADS * i;
            int r = id >> 3, c = id & 7;
            cp_async16(st + r * 128 + ((c ^ (r & 7)) << 4),
                       gA + (size_t)r * KDIM + kof + c * 8);
        }
        #pragma unroll
        for (int i = 0; i < 4; i++) {                 // B: 1024 chunks
            int id = tid + THREADS * i;
            int r = id >> 3, c = id & 7;
            cp_async16(st + ASTAGE + r * 128 + ((c ^ (r & 7)) << 4),
                       gB + (size_t)r * KDIM + kof + c * 8);
        }
    };

    // -------- per-lane fragment base addresses (relative to stage base) --------
    uint32_t afB[2], bfB[4];
    #pragma unroll
    for (int mt = 0; mt < 2; mt++) {
        int r = wm * 32 + mt * 16 + (lane & 15);
        int b = lane >> 4, k = r & 7;
        afB[mt] = r * 128 + (((b ^ (k & 1)) | (k & 6)) << 4);
    }
    #pragma unroll
    for (int p = 0; p < 4; p++) {
        int r = wn * 64 + p * 16 + (lane & 7) + ((lane >> 4) << 3);
        int b = (lane >> 3) & 1, k = r & 7;
        bfB[p] = (ASTAGE + r * 128) + (((b ^ (k & 1)) | (k & 6)) << 4);
    }

    float acc[2][8][4];
    #pragma unroll
    for (int mt = 0; mt < 2; mt++)
        #pragma unroll
        for (int nt = 0; nt < 8; nt++)
            #pragma unroll
            for (int i = 0; i < 4; i++) acc[mt][nt][i] = 0.0f;

    // -------- prologue: stages 0,1 in flight --------
    uint32_t stC = sbase, stN = sbase + SLOT, stL = sbase + 2 * SLOT;
    load_stage(0, stC); cp_commit();
    load_stage(1, stN); cp_commit();
    cp_wait<1>();
    __syncthreads();

    // -------- main K loop --------
    for (int kt = 0; kt < KITERS; kt++) {
        if (kt) bar_sync_1();   // all kt-1 arrives seen: stL free, stage-kt data published
        if (kt + 2 < KITERS) load_stage(kt + 2, stL);
        cp_commit();  // always commit to keep group accounting uniform

        #pragma unroll
        for (int s = 0; s < 3; s++) {                 // k16 steps 0..2
            const uint32_t sx = (uint32_t)(s << 5);
            uint32_t af[2][4], bf[8][2];
            #pragma unroll
            for (int mt = 0; mt < 2; mt++)
                ldsm_x4(af[mt], stC + (afB[mt] ^ sx));
            #pragma unroll
            for (int p = 0; p < 4; p++) {
                uint32_t t[4];
                ldsm_x4(t, stC + (bfB[p] ^ sx));
                bf[2 * p][0] = t[0];     bf[2 * p][1] = t[1];
                bf[2 * p + 1][0] = t[2]; bf[2 * p + 1][1] = t[3];
            }
            #pragma unroll
            for (int mt = 0; mt < 2; mt++)
                #pragma unroll
                for (int nt = 0; nt < 8; nt++)
                    mma_f16(acc[mt][nt], af[mt], bf[nt]);
        }

        // ----- step s=3: LDSM, publish (non-blocking), then register-only MMAs -----
        {
            const uint32_t sx = 3u << 5;
            uint32_t af[2][4], bf[8][2];
            #pragma unroll
            for (int mt = 0; mt < 2; mt++)
                ldsm_x4(af[mt], stC + (afB[mt] ^ sx));
            #pragma unroll
            for (int p = 0; p < 4; p++) {
                uint32_t t[4];
                ldsm_x4(t, stC + (bfB[p] ^ sx));
                bf[2 * p][0] = t[0];     bf[2 * p][1] = t[1];
                bf[2 * p + 1][0] = t[2]; bf[2 * p + 1][1] = t[3];
            }
            cp_wait<1>();      // my stage-(kt+1) cp.async group complete
            bar_arrive_1();    // non-blocking: reads of stC done + data landed
            #pragma unroll
            for (int mt = 0; mt < 2; mt++)
                #pragma unroll
                for (int nt = 0; nt < 8; nt++)
                    mma_f16(acc[mt][nt], af[mt], bf[nt]);
        }

        uint32_t t = stC; stC = stN; stN = stL; stL = t;
    }
    cp_wait<0>();  // drain tail groups before exit

    // -------- epilogue: bias add + float2 stores --------
    const int r  = lane >> 2;
    const int c2 = (lane & 3) * 2;
    const float* bp = bias + n0 + wn * 64;
    float* op = out + (size_t)(m0 + wm * 32) * NDIM + n0 + wn * 64;

    #pragma unroll
    for (int mt = 0; mt < 2; mt++) {
        #pragma unroll
        for (int nt = 0; nt < 8; nt++) {
            int n = nt * 8 + c2;
            float b0 = __ldg(bp + n), b1 = __ldg(bp + n + 1);
            float2 v0 = {acc[mt][nt][0] + b0, acc[mt][nt][1] + b1};
            float2 v1 = {acc[mt][nt][2] + b0, acc[mt][nt][3] + b1};
            *reinterpret_cast<float2*>(op + (size_t)(mt * 16 + r) * NDIM + n) = v0;
            *reinterpret_cast<float2*>(op + (size_t)(mt * 16 + r + 8) * NDIM + n) = v1;
        }
    }
}

// ---------------- host ----------------
extern "C" void kernel_launch(void* const* d_in, const int* in_sizes, int n_in,
                              void* d_out, int out_size) {
    const float* x    = (const float*)d_in[0];
    const float* w    = (const float*)d_in[1];
    const float* bias = (const float*)d_in[2];
    const float* msk  = (const float*)d_in[3];
    float* out = (float*)d_out;

    void* wm_ptr = nullptr;
    void* xr_ptr = nullptr;
    cudaGetSymbolAddress(&wm_ptr, g_wm);
    cudaGetSymbolAddress(&xr_ptr, g_xr);

    // prep: W*M and x converted to fp16 (same 11-bit mantissa as the tf32 path)
    int n4 = (KDIM * NDIM) / 4;
    prep_kernel<<<4096, 256>>>((const float4*)w, (const float4*)msk, (const float4*)x,
                               (uint2*)wm_ptr, (uint2*)xr_ptr, n4);

    cudaFuncSetAttribute(gemm_kernel, cudaFuncAttributeMaxDynamicSharedMemorySize,
                         (int)SMEM_TOTAL);

    // m fastest in blockIdx.x: each ~296-CTA wave covers all 32 m-tiles for ~9 n-tiles,
    // keeping the 32MB fp16 x matrix + active B panels L2-resident.
    dim3 grid(MDIM / BM, NDIM / BN, 1);  // (32, 32)
    gemm_kernel<<<grid, THREADS, SMEM_TOTAL>>>((const __half*)xr_ptr, (const __half*)wm_ptr,
                                               bias, out);
}